// round 3
// baseline (speedup 1.0000x reference)
#include <cuda_runtime.h>
#include <cstdint>

#define N_NODES 50000
#define X_DIMS 256
#define Y_DIMS 64

// ---------------- scratch (no cudaMalloc allowed) ----------------
__device__ int   g_row_ptr[N_NODES + 1];
__device__ float g_x1[(size_t)N_NODES * X_DIMS];
__device__ float g_x2[(size_t)N_NODES * X_DIMS];
__device__ float g_y1[(size_t)N_NODES * Y_DIMS];
__device__ float g_y2[(size_t)N_NODES * Y_DIMS];

// ---------------- CSR row_ptr from sorted COO row ----------------
__global__ void build_rowptr_kernel(const int* __restrict__ row, int E, int n)
{
    int r = blockIdx.x * blockDim.x + threadIdx.x;
    if (r > n) return;
    int lo = 0, hi = E;
    while (lo < hi) {
        int mid = (lo + hi) >> 1;
        if (row[mid] < r) lo = mid + 1; else hi = mid;
    }
    g_row_ptr[r] = lo;
}

// ---------------- vector row helpers (D=256, 32-lane rows) ----------------
__device__ __forceinline__ void load_row8(const float* __restrict__ p, int lane, float (&v)[8])
{
    float4 a = *(const float4*)(p + lane * 4);
    float4 b = *(const float4*)(p + 128 + lane * 4);
    v[0]=a.x; v[1]=a.y; v[2]=a.z; v[3]=a.w;
    v[4]=b.x; v[5]=b.y; v[6]=b.z; v[7]=b.w;
}
__device__ __forceinline__ void store_row8(float* __restrict__ p, int lane, const float (&v)[8])
{
    *(float4*)(p + lane * 4)       = make_float4(v[0], v[1], v[2], v[3]);
    *(float4*)(p + 128 + lane * 4) = make_float4(v[4], v[5], v[6], v[7]);
}

// ---------------- X propagation: D=256, one warp/row, U edges in flight ----
template <int U>
__global__ void __launch_bounds__(256) prop_x_kernel(
    const float* __restrict__ feats,
    const int*   __restrict__ col,
    const float* __restrict__ sigmas, int sidx,
    float* __restrict__ out, int n)
{
    constexpr int C = 8;
    int gw   = (int)((blockIdx.x * 256u + threadIdx.x) >> 5);
    int lane = threadIdx.x & 31;
    if (gw >= n) return;

    float sg = sigmas[sidx];
    float inv_s2 = 1.0f / (sg * sg);

    int e0 = g_row_ptr[gw];
    int e1 = g_row_ptr[gw + 1];

    float fr[C], acc[C];
    load_row8(feats + (size_t)gw * X_DIMS, lane, fr);
#pragma unroll
    for (int i = 0; i < C; i++) acc[i] = 0.0f;
    float den = 0.0f;

    int e = e0;
    for (; e + U <= e1; e += U) {
        int cs[U];
#pragma unroll
        for (int j = 0; j < U; j++) cs[j] = __ldg(col + e + j);

        float fc[U][C];
#pragma unroll
        for (int j = 0; j < U; j++)
            load_row8(feats + (size_t)cs[j] * X_DIMS, lane, fc[j]);

        float pw[U];
#pragma unroll
        for (int j = 0; j < U; j++) {
            float p = 0.0f;
#pragma unroll
            for (int i = 0; i < C; i++) {
                float d = fr[i] - fc[j][i];
                p = fmaf(d, d, p);
            }
            pw[j] = p;
        }
#pragma unroll
        for (int o = 16; o > 0; o >>= 1) {
#pragma unroll
            for (int j = 0; j < U; j++)
                pw[j] += __shfl_xor_sync(0xffffffffu, pw[j], o);
        }
#pragma unroll
        for (int j = 0; j < U; j++) {
            float val = __expf(-pw[j] * inv_s2);
            den += val;
#pragma unroll
            for (int i = 0; i < C; i++) acc[i] = fmaf(val, fc[j][i], acc[i]);
        }
    }
    for (; e < e1; e++) {
        int c = __ldg(col + e);
        float fc[C];
        load_row8(feats + (size_t)c * X_DIMS, lane, fc);
        float p = 0.0f;
#pragma unroll
        for (int i = 0; i < C; i++) {
            float d = fr[i] - fc[i];
            p = fmaf(d, d, p);
        }
#pragma unroll
        for (int o = 16; o > 0; o >>= 1)
            p += __shfl_xor_sync(0xffffffffu, p, o);
        float val = __expf(-p * inv_s2);
        den += val;
#pragma unroll
        for (int i = 0; i < C; i++) acc[i] = fmaf(val, fc[i], acc[i]);
    }

    float inv = (den > 0.0f) ? (1.0f / den) : 0.0f;
#pragma unroll
    for (int i = 0; i < C; i++) acc[i] *= inv;
    store_row8(out + (size_t)gw * X_DIMS, lane, acc);
}

// ---------------- Y propagation: D=64, warp = 4 groups x 8 lanes ----------
// Each 8-lane group owns one edge (8 floats/lane); the 3-level in-group
// shuffle reduction is shared by 4 edges; acc/den combined across groups
// once per row.
__global__ void __launch_bounds__(256) prop_y_kernel(
    const float* __restrict__ feats,
    const int*   __restrict__ col,
    const float* __restrict__ sigmas, int sidx,
    float* __restrict__ out, int n)
{
    int gw   = (int)((blockIdx.x * 256u + threadIdx.x) >> 5);
    int lane = threadIdx.x & 31;
    if (gw >= n) return;
    int sub = lane & 7;    // dim slot within group
    int grp = lane >> 3;   // edge slot 0..3

    float sg = sigmas[sidx];
    float inv_s2 = 1.0f / (sg * sg);

    int e0 = g_row_ptr[gw];
    int e1 = g_row_ptr[gw + 1];

    const float* frp = feats + (size_t)gw * Y_DIMS + sub * 8;
    float4 ra = *(const float4*)frp;
    float4 rb = *(const float4*)(frp + 4);
    float fr[8] = { ra.x, ra.y, ra.z, ra.w, rb.x, rb.y, rb.z, rb.w };

    float acc[8];
#pragma unroll
    for (int i = 0; i < 8; i++) acc[i] = 0.0f;
    float den = 0.0f;

    for (int e = e0; e < e1; e += 4) {
        int  eg  = e + grp;
        bool act = eg < e1;
        int  c   = act ? __ldg(col + eg) : 0;

        const float* fcp = feats + (size_t)c * Y_DIMS + sub * 8;
        float4 a = *(const float4*)fcp;
        float4 b = *(const float4*)(fcp + 4);
        float fc[8] = { a.x, a.y, a.z, a.w, b.x, b.y, b.z, b.w };

        float pw = 0.0f;
#pragma unroll
        for (int i = 0; i < 8; i++) {
            float d = fr[i] - fc[i];
            pw = fmaf(d, d, pw);
        }
        // reduce within the 8-lane group (offsets stay inside the group)
        pw += __shfl_xor_sync(0xffffffffu, pw, 1);
        pw += __shfl_xor_sync(0xffffffffu, pw, 2);
        pw += __shfl_xor_sync(0xffffffffu, pw, 4);

        float val = __expf(-pw * inv_s2);
        val = act ? val : 0.0f;
        den += val;
#pragma unroll
        for (int i = 0; i < 8; i++) acc[i] = fmaf(val, fc[i], acc[i]);
    }

    // combine the 4 groups' partials (once per row)
#pragma unroll
    for (int o = 8; o <= 16; o <<= 1) {
        den += __shfl_xor_sync(0xffffffffu, den, o);
#pragma unroll
        for (int i = 0; i < 8; i++)
            acc[i] += __shfl_xor_sync(0xffffffffu, acc[i], o);
    }

    float inv = (den > 0.0f) ? (1.0f / den) : 0.0f;
    if (grp == 0) {
        float* op = out + (size_t)gw * Y_DIMS + sub * 8;
        *(float4*)op       = make_float4(acc[0]*inv, acc[1]*inv, acc[2]*inv, acc[3]*inv);
        *(float4*)(op + 4) = make_float4(acc[4]*inv, acc[5]*inv, acc[6]*inv, acc[7]*inv);
    }
}

// ---------------- tf32 tensor-core GEMM: [M,896] @ [896,64] ----------------
#define BM 128
#define BN 64
#define BK 32
#define AP (BK + 4)
#define BP (BN + 8)

__device__ __forceinline__ uint32_t f2tf32(float f)
{
    uint32_t u;
    asm("cvt.rna.tf32.f32 %0, %1;" : "=r"(u) : "f"(f));
    return u;
}

__device__ __forceinline__ void mma_tf32(float (&c)[4], const uint32_t (&a)[4], const uint32_t (&b)[2])
{
    asm volatile(
        "mma.sync.aligned.m16n8k8.row.col.f32.tf32.tf32.f32 "
        "{%0,%1,%2,%3}, {%4,%5,%6,%7}, {%8,%9}, {%0,%1,%2,%3};\n"
        : "+f"(c[0]), "+f"(c[1]), "+f"(c[2]), "+f"(c[3])
        : "r"(a[0]), "r"(a[1]), "r"(a[2]), "r"(a[3]), "r"(b[0]), "r"(b[1]));
}

__global__ void __launch_bounds__(256) gemm_tf32_kernel(
    const float* __restrict__ x,
    const float* __restrict__ x1,
    const float* __restrict__ x2,
    const float* __restrict__ y1,
    const float* __restrict__ y2,
    const float* __restrict__ W,
    float* __restrict__ out, int M)
{
    __shared__ float As[BM][AP];
    __shared__ float Bs[BK][BP];

    int tid  = threadIdx.x;
    int lane = tid & 31;
    int wid  = tid >> 5;
    int wm = (wid >> 1) * 32;
    int wn = (wid & 1) * 32;
    int g  = lane >> 2;
    int tk = lane & 3;
    int row0 = blockIdx.x * BM;

    float c[2][4][4];
#pragma unroll
    for (int mt = 0; mt < 2; mt++)
#pragma unroll
        for (int nt = 0; nt < 4; nt++)
#pragma unroll
            for (int q = 0; q < 4; q++) c[mt][nt][q] = 0.0f;

    const float* segs[5]   = { x, x1, x2, y1, y2 };
    const int    widths[5] = { X_DIMS, X_DIMS, X_DIMS, Y_DIMS, Y_DIMS };

    int kglobal = 0;
    for (int s = 0; s < 5; s++) {
        const float* A = segs[s];
        int width = widths[s];
        for (int kc = 0; kc < width; kc += BK) {
#pragma unroll
            for (int i = 0; i < 4; i++) {
                int idx = i * 256 + tid;
                int r  = idx >> 3;
                int kg = (idx & 7) * 4;
                int grow = row0 + r;
                float4 v = make_float4(0.f, 0.f, 0.f, 0.f);
                if (grow < M)
                    v = *(const float4*)(A + (size_t)grow * width + kc + kg);
                *(float4*)&As[r][kg] = v;
            }
#pragma unroll
            for (int i = 0; i < 2; i++) {
                int idx = i * 256 + tid;
                int k = idx >> 4;
                int j = (idx & 15) * 4;
                float4 v = *(const float4*)(W + (size_t)(kglobal + kc + k) * BN + j);
                *(float4*)&Bs[k][j] = v;
            }
            __syncthreads();

#pragma unroll
            for (int kk = 0; kk < BK; kk += 8) {
                uint32_t a[2][4];
#pragma unroll
                for (int mt = 0; mt < 2; mt++) {
                    int mrow = wm + mt * 16 + g;
                    a[mt][0] = f2tf32(As[mrow][kk + tk]);
                    a[mt][1] = f2tf32(As[mrow + 8][kk + tk]);
                    a[mt][2] = f2tf32(As[mrow][kk + tk + 4]);
                    a[mt][3] = f2tf32(As[mrow + 8][kk + tk + 4]);
                }
                uint32_t b[4][2];
#pragma unroll
                for (int nt = 0; nt < 4; nt++) {
                    int ncol = wn + nt * 8 + g;
                    b[nt][0] = f2tf32(Bs[kk + tk][ncol]);
                    b[nt][1] = f2tf32(Bs[kk + tk + 4][ncol]);
                }
#pragma unroll
                for (int mt = 0; mt < 2; mt++)
#pragma unroll
                    for (int nt = 0; nt < 4; nt++)
                        mma_tf32(c[mt][nt], a[mt], b[nt]);
            }
            __syncthreads();
        }
        kglobal += width;
    }

#pragma unroll
    for (int mt = 0; mt < 2; mt++) {
#pragma unroll
        for (int nt = 0; nt < 4; nt++) {
            int r0 = row0 + wm + mt * 16 + g;
            int cc = wn + nt * 8 + 2 * tk;
            if (r0 < M)
                *(float2*)(out + (size_t)r0 * BN + cc) = make_float2(c[mt][nt][0], c[mt][nt][1]);
            if (r0 + 8 < M)
                *(float2*)(out + (size_t)(r0 + 8) * BN + cc) = make_float2(c[mt][nt][2], c[mt][nt][3]);
        }
    }
}

// ---------------- launch ----------------
extern "C" void kernel_launch(void* const* d_in, const int* in_sizes, int n_in,
                              void* d_out, int out_size)
{
    const float* x   = (const float*)d_in[0];
    const float* y   = (const float*)d_in[1];
    const float* W   = (const float*)d_in[2];
    const float* sig = (const float*)d_in[3];
    const int*   row = (const int*)  d_in[4];
    const int*   col = (const int*)  d_in[5];

    int N = in_sizes[0] / X_DIMS;
    int E = in_sizes[4];

    float *px1, *px2, *py1, *py2;
    cudaGetSymbolAddress((void**)&px1, g_x1);
    cudaGetSymbolAddress((void**)&px2, g_x2);
    cudaGetSymbolAddress((void**)&py1, g_y1);
    cudaGetSymbolAddress((void**)&py2, g_y2);

    build_rowptr_kernel<<<(N + 1 + 255) / 256, 256>>>(row, E, N);

    int pb = (N * 32 + 255) / 256;   // one warp per row
    prop_x_kernel<4><<<pb, 256>>>(x,   col, sig, 0, px1, N);
    prop_x_kernel<4><<<pb, 256>>>(px1, col, sig, 1, px2, N);
    prop_y_kernel<<<pb, 256>>>(y,   col, sig, 2, py1, N);
    prop_y_kernel<<<pb, 256>>>(py1, col, sig, 3, py2, N);

    gemm_tf32_kernel<<<(N + BM - 1) / BM, 256>>>(x, px1, px2, py1, py2, W,
                                                 (float*)d_out, N);
}

// round 4
// speedup vs baseline: 1.0580x; 1.0580x over previous
#include <cuda_runtime.h>
#include <cstdint>

#define N_NODES 50000
#define X_DIMS 256
#define Y_DIMS 64

// ---------------- scratch (no cudaMalloc allowed) ----------------
__device__ int   g_row_ptr[N_NODES + 1];
__device__ float g_x1[(size_t)N_NODES * X_DIMS];
__device__ float g_x2[(size_t)N_NODES * X_DIMS];
__device__ float g_y1[(size_t)N_NODES * Y_DIMS];
__device__ float g_y2[(size_t)N_NODES * Y_DIMS];

// ---------------- CSR row_ptr from sorted COO row ----------------
__global__ void build_rowptr_kernel(const int* __restrict__ row, int E, int n)
{
    int r = blockIdx.x * blockDim.x + threadIdx.x;
    if (r > n) return;
    int lo = 0, hi = E;
    while (lo < hi) {
        int mid = (lo + hi) >> 1;
        if (row[mid] < r) lo = mid + 1; else hi = mid;
    }
    g_row_ptr[r] = lo;
}

// ---------------- row load/store helpers ----------------
__device__ __forceinline__ void load_row(const float* __restrict__ p, int lane, float (&v)[8])
{
    float4 a = *(const float4*)(p + lane * 4);
    float4 b = *(const float4*)(p + 128 + lane * 4);
    v[0]=a.x; v[1]=a.y; v[2]=a.z; v[3]=a.w;
    v[4]=b.x; v[5]=b.y; v[6]=b.z; v[7]=b.w;
}
__device__ __forceinline__ void load_row(const float* __restrict__ p, int lane, float (&v)[2])
{
    float2 a = *(const float2*)(p + lane * 2);
    v[0]=a.x; v[1]=a.y;
}
__device__ __forceinline__ void store_row(float* __restrict__ p, int lane, const float (&v)[8])
{
    *(float4*)(p + lane * 4)       = make_float4(v[0], v[1], v[2], v[3]);
    *(float4*)(p + 128 + lane * 4) = make_float4(v[4], v[5], v[6], v[7]);
}
__device__ __forceinline__ void store_row(float* __restrict__ p, int lane, const float (&v)[2])
{
    *(float2*)(p + lane * 2) = make_float2(v[0], v[1]);
}

// ---------------- core prop body: one warp per row, U edges in flight ------
template <int D, int U>
__device__ __forceinline__ void prop_row(
    const float* __restrict__ feats,
    const int*   __restrict__ col,
    float inv_s2, float* __restrict__ out, int gw, int lane)
{
    constexpr int C = D / 32;
    int e0 = g_row_ptr[gw];
    int e1 = g_row_ptr[gw + 1];

    float fr[C], acc[C];
    load_row(feats + (size_t)gw * D, lane, fr);
#pragma unroll
    for (int i = 0; i < C; i++) acc[i] = 0.0f;
    float den = 0.0f;

    int e = e0;
    for (; e + U <= e1; e += U) {
        int cs[U];
#pragma unroll
        for (int j = 0; j < U; j++) cs[j] = __ldg(col + e + j);

        float fc[U][C];
#pragma unroll
        for (int j = 0; j < U; j++)
            load_row(feats + (size_t)cs[j] * D, lane, fc[j]);

        float pw[U];
#pragma unroll
        for (int j = 0; j < U; j++) {
            float p = 0.0f;
#pragma unroll
            for (int i = 0; i < C; i++) {
                float d = fr[i] - fc[j][i];
                p = fmaf(d, d, p);
            }
            pw[j] = p;
        }
#pragma unroll
        for (int o = 16; o > 0; o >>= 1) {
#pragma unroll
            for (int j = 0; j < U; j++)
                pw[j] += __shfl_xor_sync(0xffffffffu, pw[j], o);
        }
#pragma unroll
        for (int j = 0; j < U; j++) {
            float val = __expf(-pw[j] * inv_s2);
            den += val;
#pragma unroll
            for (int i = 0; i < C; i++) acc[i] = fmaf(val, fc[j][i], acc[i]);
        }
    }
    for (; e < e1; e++) {
        int c = __ldg(col + e);
        float fc[C];
        load_row(feats + (size_t)c * D, lane, fc);
        float p = 0.0f;
#pragma unroll
        for (int i = 0; i < C; i++) {
            float d = fr[i] - fc[i];
            p = fmaf(d, d, p);
        }
#pragma unroll
        for (int o = 16; o > 0; o >>= 1)
            p += __shfl_xor_sync(0xffffffffu, p, o);
        float val = __expf(-p * inv_s2);
        den += val;
#pragma unroll
        for (int i = 0; i < C; i++) acc[i] = fmaf(val, fc[i], acc[i]);
    }

    float inv = (den > 0.0f) ? (1.0f / den) : 0.0f;
#pragma unroll
    for (int i = 0; i < C; i++) acc[i] *= inv;
    store_row(out + (size_t)gw * D, lane, acc);
}

// ---------------- fused X||Y propagation ----------------------------------
// Even blocks: X rows (D=256, U=2). Odd blocks: Y rows (D=64, U=4).
// Interleaving keeps both workload types co-resident on every SM so Y's
// FMA/shfl work fills issue slots left idle by X's L2-latency stalls.
__global__ void __launch_bounds__(256) prop_xy_kernel(
    const float* __restrict__ xsrc, float* __restrict__ xdst,
    const float* __restrict__ ysrc, float* __restrict__ ydst,
    const int*   __restrict__ col,
    const float* __restrict__ sigmas, int sx, int sy, int n)
{
    int bid  = blockIdx.x;
    int lane = threadIdx.x & 31;
    int gw   = (int)(((bid >> 1) * 256u + threadIdx.x) >> 5);
    if (gw >= n) return;

    if ((bid & 1) == 0) {
        float sg = sigmas[sx];
        prop_row<X_DIMS, 2>(xsrc, col, 1.0f / (sg * sg), xdst, gw, lane);
    } else {
        float sg = sigmas[sy];
        prop_row<Y_DIMS, 4>(ysrc, col, 1.0f / (sg * sg), ydst, gw, lane);
    }
}

// ---------------- tf32 tensor-core GEMM: [M,896] @ [896,64] ----------------
#define BM 128
#define BN 64
#define BK 32
#define AP (BK + 4)
#define BP (BN + 8)

__device__ __forceinline__ uint32_t f2tf32(float f)
{
    uint32_t u;
    asm("cvt.rna.tf32.f32 %0, %1;" : "=r"(u) : "f"(f));
    return u;
}

__device__ __forceinline__ void mma_tf32(float (&c)[4], const uint32_t (&a)[4], const uint32_t (&b)[2])
{
    asm volatile(
        "mma.sync.aligned.m16n8k8.row.col.f32.tf32.tf32.f32 "
        "{%0,%1,%2,%3}, {%4,%5,%6,%7}, {%8,%9}, {%0,%1,%2,%3};\n"
        : "+f"(c[0]), "+f"(c[1]), "+f"(c[2]), "+f"(c[3])
        : "r"(a[0]), "r"(a[1]), "r"(a[2]), "r"(a[3]), "r"(b[0]), "r"(b[1]));
}

__global__ void __launch_bounds__(256) gemm_tf32_kernel(
    const float* __restrict__ x,
    const float* __restrict__ x1,
    const float* __restrict__ x2,
    const float* __restrict__ y1,
    const float* __restrict__ y2,
    const float* __restrict__ W,
    float* __restrict__ out, int M)
{
    __shared__ float As[BM][AP];
    __shared__ float Bs[BK][BP];

    int tid  = threadIdx.x;
    int lane = tid & 31;
    int wid  = tid >> 5;
    int wm = (wid >> 1) * 32;
    int wn = (wid & 1) * 32;
    int g  = lane >> 2;
    int tk = lane & 3;
    int row0 = blockIdx.x * BM;

    float c[2][4][4];
#pragma unroll
    for (int mt = 0; mt < 2; mt++)
#pragma unroll
        for (int nt = 0; nt < 4; nt++)
#pragma unroll
            for (int q = 0; q < 4; q++) c[mt][nt][q] = 0.0f;

    const float* segs[5]   = { x, x1, x2, y1, y2 };
    const int    widths[5] = { X_DIMS, X_DIMS, X_DIMS, Y_DIMS, Y_DIMS };

    int kglobal = 0;
    for (int s = 0; s < 5; s++) {
        const float* A = segs[s];
        int width = widths[s];
        for (int kc = 0; kc < width; kc += BK) {
#pragma unroll
            for (int i = 0; i < 4; i++) {
                int idx = i * 256 + tid;
                int r  = idx >> 3;
                int kg = (idx & 7) * 4;
                int grow = row0 + r;
                float4 v = make_float4(0.f, 0.f, 0.f, 0.f);
                if (grow < M)
                    v = *(const float4*)(A + (size_t)grow * width + kc + kg);
                *(float4*)&As[r][kg] = v;
            }
#pragma unroll
            for (int i = 0; i < 2; i++) {
                int idx = i * 256 + tid;
                int k = idx >> 4;
                int j = (idx & 15) * 4;
                float4 v = *(const float4*)(W + (size_t)(kglobal + kc + k) * BN + j);
                *(float4*)&Bs[k][j] = v;
            }
            __syncthreads();

#pragma unroll
            for (int kk = 0; kk < BK; kk += 8) {
                uint32_t a[2][4];
#pragma unroll
                for (int mt = 0; mt < 2; mt++) {
                    int mrow = wm + mt * 16 + g;
                    a[mt][0] = f2tf32(As[mrow][kk + tk]);
                    a[mt][1] = f2tf32(As[mrow + 8][kk + tk]);
                    a[mt][2] = f2tf32(As[mrow][kk + tk + 4]);
                    a[mt][3] = f2tf32(As[mrow + 8][kk + tk + 4]);
                }
                uint32_t b[4][2];
#pragma unroll
                for (int nt = 0; nt < 4; nt++) {
                    int ncol = wn + nt * 8 + g;
                    b[nt][0] = f2tf32(Bs[kk + tk][ncol]);
                    b[nt][1] = f2tf32(Bs[kk + tk + 4][ncol]);
                }
#pragma unroll
                for (int mt = 0; mt < 2; mt++)
#pragma unroll
                    for (int nt = 0; nt < 4; nt++)
                        mma_tf32(c[mt][nt], a[mt], b[nt]);
            }
            __syncthreads();
        }
        kglobal += width;
    }

#pragma unroll
    for (int mt = 0; mt < 2; mt++) {
#pragma unroll
        for (int nt = 0; nt < 4; nt++) {
            int r0 = row0 + wm + mt * 16 + g;
            int cc = wn + nt * 8 + 2 * tk;
            if (r0 < M)
                *(float2*)(out + (size_t)r0 * BN + cc) = make_float2(c[mt][nt][0], c[mt][nt][1]);
            if (r0 + 8 < M)
                *(float2*)(out + (size_t)(r0 + 8) * BN + cc) = make_float2(c[mt][nt][2], c[mt][nt][3]);
        }
    }
}

// ---------------- launch ----------------
extern "C" void kernel_launch(void* const* d_in, const int* in_sizes, int n_in,
                              void* d_out, int out_size)
{
    const float* x   = (const float*)d_in[0];
    const float* y   = (const float*)d_in[1];
    const float* W   = (const float*)d_in[2];
    const float* sig = (const float*)d_in[3];
    const int*   row = (const int*)  d_in[4];
    const int*   col = (const int*)  d_in[5];

    int N = in_sizes[0] / X_DIMS;
    int E = in_sizes[4];

    float *px1, *px2, *py1, *py2;
    cudaGetSymbolAddress((void**)&px1, g_x1);
    cudaGetSymbolAddress((void**)&px2, g_x2);
    cudaGetSymbolAddress((void**)&py1, g_y1);
    cudaGetSymbolAddress((void**)&py2, g_y2);

    build_rowptr_kernel<<<(N + 1 + 255) / 256, 256>>>(row, E, N);

    int pb = (N * 32 + 255) / 256;     // blocks per task (warp per row)
    // fused: even blocks X, odd blocks Y
    prop_xy_kernel<<<2 * pb, 256>>>(x,   px1, y,   py1, col, sig, 0, 2, N);
    prop_xy_kernel<<<2 * pb, 256>>>(px1, px2, py1, py2, col, sig, 1, 3, N);

    gemm_tf32_kernel<<<(N + BM - 1) / BM, 256>>>(x, px1, px2, py1, py2, W,
                                                 (float*)d_out, N);
}

// round 5
// speedup vs baseline: 1.0892x; 1.0295x over previous
#include <cuda_runtime.h>
#include <cstdint>

#define N_NODES 50000
#define X_DIMS 256
#define Y_DIMS 64

// ---------------- scratch (no cudaMalloc allowed) ----------------
__device__ int   g_row_ptr[N_NODES + 1];
__device__ float g_x1[(size_t)N_NODES * X_DIMS];
__device__ float g_x2[(size_t)N_NODES * X_DIMS];
__device__ float g_y1[(size_t)N_NODES * Y_DIMS];
__device__ float g_y2[(size_t)N_NODES * Y_DIMS];
__device__ float g_sqn_x [N_NODES];
__device__ float g_sqn_y [N_NODES];
__device__ float g_sqn_x1[N_NODES];
__device__ float g_sqn_y1[N_NODES];

// ---------------- CSR row_ptr from sorted COO row ----------------
__global__ void build_rowptr_kernel(const int* __restrict__ row, int E, int n)
{
    int r = blockIdx.x * blockDim.x + threadIdx.x;
    if (r > n) return;
    int lo = 0, hi = E;
    while (lo < hi) {
        int mid = (lo + hi) >> 1;
        if (row[mid] < r) lo = mid + 1; else hi = mid;
    }
    g_row_ptr[r] = lo;
}

// ---------------- row load/store helpers ----------------
__device__ __forceinline__ void load_row(const float* __restrict__ p, int lane, float (&v)[8])
{
    float4 a = *(const float4*)(p + lane * 4);
    float4 b = *(const float4*)(p + 128 + lane * 4);
    v[0]=a.x; v[1]=a.y; v[2]=a.z; v[3]=a.w;
    v[4]=b.x; v[5]=b.y; v[6]=b.z; v[7]=b.w;
}
__device__ __forceinline__ void load_row(const float* __restrict__ p, int lane, float (&v)[2])
{
    float2 a = *(const float2*)(p + lane * 2);
    v[0]=a.x; v[1]=a.y;
}
__device__ __forceinline__ void store_row(float* __restrict__ p, int lane, const float (&v)[8])
{
    *(float4*)(p + lane * 4)       = make_float4(v[0], v[1], v[2], v[3]);
    *(float4*)(p + 128 + lane * 4) = make_float4(v[4], v[5], v[6], v[7]);
}
__device__ __forceinline__ void store_row(float* __restrict__ p, int lane, const float (&v)[2])
{
    *(float2*)(p + lane * 2) = make_float2(v[0], v[1]);
}

// ---------------- squared-norm kernel (warp per row) ----------------
template <int D>
__global__ void __launch_bounds__(256) norm_kernel(
    const float* __restrict__ feats, float* __restrict__ sqn, int n)
{
    constexpr int C = D / 32;
    int gw   = (int)((blockIdx.x * 256u + threadIdx.x) >> 5);
    int lane = threadIdx.x & 31;
    if (gw >= n) return;
    float fr[C];
    load_row(feats + (size_t)gw * D, lane, fr);
    float s = 0.0f;
#pragma unroll
    for (int i = 0; i < C; i++) s = fmaf(fr[i], fr[i], s);
#pragma unroll
    for (int o = 16; o > 0; o >>= 1)
        s += __shfl_xor_sync(0xffffffffu, s, o);
    if (lane == 0) sqn[gw] = s;
}

// ---------------- prop: warp per row, U edges in flight --------------------
// ||fr-fc||^2 = nr + nc - 2 dot(fr,fc); per-node sq-norms precomputed.
template <int D, int U, bool WN>
__global__ void __launch_bounds__(256) prop_kernel(
    const float* __restrict__ feats,
    const int*   __restrict__ col,
    const float* __restrict__ sqn_src,
    float*       __restrict__ sqn_dst,
    const float* __restrict__ sigmas, int sidx,
    float* __restrict__ out, int n)
{
    constexpr int C = D / 32;
    int gw   = (int)((blockIdx.x * 256u + threadIdx.x) >> 5);
    int lane = threadIdx.x & 31;
    if (gw >= n) return;

    float sg = sigmas[sidx];
    float inv_s2 = 1.0f / (sg * sg);
    float t2 = 2.0f * inv_s2;

    int e0 = g_row_ptr[gw];
    int e1 = g_row_ptr[gw + 1];

    float fr[C], acc[C];
    load_row(feats + (size_t)gw * D, lane, fr);
    float bnr = -sqn_src[gw] * inv_s2;            // -nr/s^2 (row-uniform)
#pragma unroll
    for (int i = 0; i < C; i++) acc[i] = 0.0f;
    float den = 0.0f;

    int e = e0;
    for (; e + U <= e1; e += U) {
        int cs[U];
        float nc[U];
#pragma unroll
        for (int j = 0; j < U; j++) {
            cs[j] = __ldg(col + e + j);
            nc[j] = __ldg(sqn_src + cs[j]);
        }
        float fc[U][C];
#pragma unroll
        for (int j = 0; j < U; j++)
            load_row(feats + (size_t)cs[j] * D, lane, fc[j]);

        float dt[U];
#pragma unroll
        for (int j = 0; j < U; j++) {
            float d = 0.0f;
#pragma unroll
            for (int i = 0; i < C; i++) d = fmaf(fr[i], fc[j][i], d);
            dt[j] = d;
        }
#pragma unroll
        for (int o = 16; o > 0; o >>= 1) {
#pragma unroll
            for (int j = 0; j < U; j++)
                dt[j] += __shfl_xor_sync(0xffffffffu, dt[j], o);
        }
#pragma unroll
        for (int j = 0; j < U; j++) {
            // arg = (2*dot - nr - nc)/s^2
            float val = __expf(fmaf(t2, dt[j], fmaf(-inv_s2, nc[j], bnr)));
            den += val;
#pragma unroll
            for (int i = 0; i < C; i++) acc[i] = fmaf(val, fc[j][i], acc[i]);
        }
    }
    for (; e < e1; e++) {
        int c = __ldg(col + e);
        float ncv = __ldg(sqn_src + c);
        float fc[C];
        load_row(feats + (size_t)c * D, lane, fc);
        float d = 0.0f;
#pragma unroll
        for (int i = 0; i < C; i++) d = fmaf(fr[i], fc[i], d);
#pragma unroll
        for (int o = 16; o > 0; o >>= 1)
            d += __shfl_xor_sync(0xffffffffu, d, o);
        float val = __expf(fmaf(t2, d, fmaf(-inv_s2, ncv, bnr)));
        den += val;
#pragma unroll
        for (int i = 0; i < C; i++) acc[i] = fmaf(val, fc[i], acc[i]);
    }

    float inv = (den > 0.0f) ? (1.0f / den) : 0.0f;
#pragma unroll
    for (int i = 0; i < C; i++) acc[i] *= inv;
    store_row(out + (size_t)gw * D, lane, acc);

    if (WN) {   // free squared-norm of the output row for the next iteration
        float s = 0.0f;
#pragma unroll
        for (int i = 0; i < C; i++) s = fmaf(acc[i], acc[i], s);
#pragma unroll
        for (int o = 16; o > 0; o >>= 1)
            s += __shfl_xor_sync(0xffffffffu, s, o);
        if (lane == 0) sqn_dst[gw] = s;
    }
}

// ---------------- tf32 GEMM v2: [M,896] @ [896,64] -------------------------
// tf32 conversion at smem-store time; double-buffered with register prefetch.
#define BM 128
#define BN 64
#define BK 32
#define AP (BK + 4)       // 36: LDS bank = 4g+tk, conflict-free
#define BP (BN + 8)       // 72: LDS bank = 8tk+g, conflict-free
#define NT 28             // 896 / BK
#define SMEM_GEMM (2 * (BM * AP + BK * BP) * 4)

__device__ __forceinline__ uint32_t f2tf32(float f)
{
    uint32_t u;
    asm("cvt.rna.tf32.f32 %0, %1;" : "=r"(u) : "f"(f));
    return u;
}

__device__ __forceinline__ void mma_tf32(float (&c)[4], const uint32_t (&a)[4], const uint32_t (&b)[2])
{
    asm volatile(
        "mma.sync.aligned.m16n8k8.row.col.f32.tf32.tf32.f32 "
        "{%0,%1,%2,%3}, {%4,%5,%6,%7}, {%8,%9}, {%0,%1,%2,%3};\n"
        : "+f"(c[0]), "+f"(c[1]), "+f"(c[2]), "+f"(c[3])
        : "r"(a[0]), "r"(a[1]), "r"(a[2]), "r"(a[3]), "r"(b[0]), "r"(b[1]));
}

// tile t -> (segment base + column offset, row width)
__device__ __forceinline__ const float* tile_base(
    int t, const float* x, const float* x1, const float* x2,
    const float* y1, const float* y2, int& width)
{
    if (t < 8)  { width = X_DIMS; return x  + (t << 5); }
    if (t < 16) { width = X_DIMS; return x1 + ((t - 8) << 5); }
    if (t < 24) { width = X_DIMS; return x2 + ((t - 16) << 5); }
    if (t < 26) { width = Y_DIMS; return y1 + ((t - 24) << 5); }
    width = Y_DIMS; return y2 + ((t - 26) << 5);
}

__global__ void __launch_bounds__(256) gemm_tf32_kernel(
    const float* __restrict__ x,
    const float* __restrict__ x1,
    const float* __restrict__ x2,
    const float* __restrict__ y1,
    const float* __restrict__ y2,
    const float* __restrict__ W,
    float* __restrict__ out, int M)
{
    extern __shared__ uint32_t dsm[];
    uint32_t (*As)[BM][AP] = (uint32_t (*)[BM][AP])dsm;
    uint32_t (*Bs)[BK][BP] = (uint32_t (*)[BK][BP])(dsm + 2 * BM * AP);

    int tid  = threadIdx.x;
    int lane = tid & 31;
    int wid  = tid >> 5;
    int wm = (wid >> 1) * 32;
    int wn = (wid & 1) * 32;
    int g  = lane >> 2;
    int tk = lane & 3;
    int row0 = blockIdx.x * BM;

    // A-load mapping: 8 threads per row, 4 rows per thread
    int ar = tid >> 3;
    int kg = (tid & 7) * 4;
    // B-load mapping: 16 threads per k-row, 2 k per thread
    int bk_ = tid >> 4;
    int bj  = (tid & 15) * 4;

    float4 pa[4];
    float4 pb[2];

    float c[2][4][4];
#pragma unroll
    for (int mt = 0; mt < 2; mt++)
#pragma unroll
        for (int nt = 0; nt < 4; nt++)
#pragma unroll
            for (int q = 0; q < 4; q++) c[mt][nt][q] = 0.0f;

#define LDG_TILE(t)                                                        \
    do {                                                                   \
        int width_;                                                        \
        const float* base_ = tile_base((t), x, x1, x2, y1, y2, width_);    \
        _Pragma("unroll")                                                  \
        for (int i = 0; i < 4; i++) {                                      \
            int grow = row0 + ar + 32 * i;                                 \
            pa[i] = make_float4(0.f, 0.f, 0.f, 0.f);                       \
            if (grow < M)                                                  \
                pa[i] = *(const float4*)(base_ + (size_t)grow * width_ + kg);\
        }                                                                  \
        _Pragma("unroll")                                                  \
        for (int i = 0; i < 2; i++) {                                      \
            int k_ = bk_ + 16 * i;                                         \
            pb[i] = *(const float4*)(W + (size_t)((t) * BK + k_) * BN + bj);\
        }                                                                  \
    } while (0)

#define STS_TILE(buf)                                                      \
    do {                                                                   \
        _Pragma("unroll")                                                  \
        for (int i = 0; i < 4; i++) {                                      \
            int r_ = ar + 32 * i;                                          \
            As[buf][r_][kg + 0] = f2tf32(pa[i].x);                         \
            As[buf][r_][kg + 1] = f2tf32(pa[i].y);                         \
            As[buf][r_][kg + 2] = f2tf32(pa[i].z);                         \
            As[buf][r_][kg + 3] = f2tf32(pa[i].w);                         \
        }                                                                  \
        _Pragma("unroll")                                                  \
        for (int i = 0; i < 2; i++) {                                      \
            int k_ = bk_ + 16 * i;                                         \
            Bs[buf][k_][bj + 0] = f2tf32(pb[i].x);                         \
            Bs[buf][k_][bj + 1] = f2tf32(pb[i].y);                         \
            Bs[buf][k_][bj + 2] = f2tf32(pb[i].z);                         \
            Bs[buf][k_][bj + 3] = f2tf32(pb[i].w);                         \
        }                                                                  \
    } while (0)

    LDG_TILE(0);
    STS_TILE(0);
    __syncthreads();

    for (int t = 0; t < NT; t++) {
        if (t + 1 < NT) LDG_TILE(t + 1);     // global loads fly over the MMAs

        int buf = t & 1;
#pragma unroll
        for (int kk = 0; kk < BK; kk += 8) {
            uint32_t a[2][4];
#pragma unroll
            for (int mt = 0; mt < 2; mt++) {
                int mrow = wm + mt * 16 + g;
                a[mt][0] = As[buf][mrow][kk + tk];
                a[mt][1] = As[buf][mrow + 8][kk + tk];
                a[mt][2] = As[buf][mrow][kk + tk + 4];
                a[mt][3] = As[buf][mrow + 8][kk + tk + 4];
            }
            uint32_t b[4][2];
#pragma unroll
            for (int nt = 0; nt < 4; nt++) {
                int ncol = wn + nt * 8 + g;
                b[nt][0] = Bs[buf][kk + tk][ncol];
                b[nt][1] = Bs[buf][kk + tk + 4][ncol];
            }
#pragma unroll
            for (int mt = 0; mt < 2; mt++)
#pragma unroll
                for (int nt = 0; nt < 4; nt++)
                    mma_tf32(c[mt][nt], a[mt], b[nt]);
        }

        if (t + 1 < NT) {
            STS_TILE((t + 1) & 1);
            __syncthreads();
        }
    }

#pragma unroll
    for (int mt = 0; mt < 2; mt++) {
#pragma unroll
        for (int nt = 0; nt < 4; nt++) {
            int r0 = row0 + wm + mt * 16 + g;
            int cc = wn + nt * 8 + 2 * tk;
            if (r0 < M)
                *(float2*)(out + (size_t)r0 * BN + cc) = make_float2(c[mt][nt][0], c[mt][nt][1]);
            if (r0 + 8 < M)
                *(float2*)(out + (size_t)(r0 + 8) * BN + cc) = make_float2(c[mt][nt][2], c[mt][nt][3]);
        }
    }
}

// ---------------- launch ----------------
extern "C" void kernel_launch(void* const* d_in, const int* in_sizes, int n_in,
                              void* d_out, int out_size)
{
    const float* x   = (const float*)d_in[0];
    const float* y   = (const float*)d_in[1];
    const float* W   = (const float*)d_in[2];
    const float* sig = (const float*)d_in[3];
    const int*   row = (const int*)  d_in[4];
    const int*   col = (const int*)  d_in[5];

    int N = in_sizes[0] / X_DIMS;
    int E = in_sizes[4];

    float *px1, *px2, *py1, *py2, *nx, *ny, *nx1, *ny1;
    cudaGetSymbolAddress((void**)&px1, g_x1);
    cudaGetSymbolAddress((void**)&px2, g_x2);
    cudaGetSymbolAddress((void**)&py1, g_y1);
    cudaGetSymbolAddress((void**)&py2, g_y2);
    cudaGetSymbolAddress((void**)&nx,  g_sqn_x);
    cudaGetSymbolAddress((void**)&ny,  g_sqn_y);
    cudaGetSymbolAddress((void**)&nx1, g_sqn_x1);
    cudaGetSymbolAddress((void**)&ny1, g_sqn_y1);

    cudaFuncSetAttribute(gemm_tf32_kernel,
                         cudaFuncAttributeMaxDynamicSharedMemorySize, SMEM_GEMM);

    build_rowptr_kernel<<<(N + 1 + 255) / 256, 256>>>(row, E, N);

    int pb = (N * 32 + 255) / 256;   // one warp per row
    norm_kernel<X_DIMS><<<pb, 256>>>(x, nx, N);
    norm_kernel<Y_DIMS><<<pb, 256>>>(y, ny, N);

    prop_kernel<X_DIMS, 2, true ><<<pb, 256>>>(x,   col, nx,  nx1, sig, 0, px1, N);
    prop_kernel<Y_DIMS, 4, true ><<<pb, 256>>>(y,   col, ny,  ny1, sig, 2, py1, N);
    prop_kernel<X_DIMS, 2, false><<<pb, 256>>>(px1, col, nx1, nullptr, sig, 1, px2, N);
    prop_kernel<Y_DIMS, 4, false><<<pb, 256>>>(py1, col, ny1, nullptr, sig, 3, py2, N);

    gemm_tf32_kernel<<<(N + BM - 1) / BM, 256, SMEM_GEMM>>>(
        x, px1, px2, py1, py2, W, (float*)d_out, N);
}